// round 7
// baseline (speedup 1.0000x reference)
#include <cuda_runtime.h>
#include <cuda_fp16.h>
#include <cstdint>

#define BB 128
#define TQ 64
#define TK 200
#define TKP 224
#define DD 64
#define HH 10
#define NTHREADS 1024

#define TSTRIDE 464            // seqT row stride bytes (fp16, 224 cols + pad)
#define ASTRIDE 144            // A / SEQK row stride bytes (72 fp16)
#define PSTRIDE 432            // P row stride bytes (216 fp16)

// ---- smem byte offsets ----
#define SEQT_B   0             // fp16 seq transposed [64d][464B]      29,696
#define P_B      0             // alias: fp16 P [64t][432B] (phase D/E)
#define SEQK_B   29696         // fp16 seq k-major [208][144B]         29,952
#define ABUF_B   59648         // fp16 A[10][64t][144B]                92,160
#define TGT_B    151808        // float [64][65]                       16,640
#define AW_B     168448        // float [10][64] (x256)                 2,560
#define DEC_B    171008        // float [224]                             896
#define VAL_B    171904        // float [224]                             896
#define AB_B     172800        // float [16]
#define AO_B     172864        // float [16]
#define FR_B     172928        // float [64]
#define FI_B     173184        // float [64]
#define PART_B   173440        // float [64][8] row partial sums        2,048
#define SMEM_TOTAL_B 175488

static __device__ __forceinline__ uint32_t smem_u32(const void* p) {
    uint32_t a;
    asm("{ .reg .u64 t; cvta.to.shared.u64 t, %1; cvt.u32.u64 %0, t; }" : "=r"(a) : "l"(p));
    return a;
}
static __device__ __forceinline__ void ldsm_x4(uint32_t* r, uint32_t addr) {
    asm volatile("ldmatrix.sync.aligned.m8n8.x4.shared.b16 {%0,%1,%2,%3}, [%4];"
                 : "=r"(r[0]), "=r"(r[1]), "=r"(r[2]), "=r"(r[3]) : "r"(addr));
}
static __device__ __forceinline__ void ldsm_x4t(uint32_t* r, uint32_t addr) {
    asm volatile("ldmatrix.sync.aligned.m8n8.x4.trans.shared.b16 {%0,%1,%2,%3}, [%4];"
                 : "=r"(r[0]), "=r"(r[1]), "=r"(r[2]), "=r"(r[3]) : "r"(addr));
}
static __device__ __forceinline__ void ldsm_x2t(uint32_t* r, uint32_t addr) {
    asm volatile("ldmatrix.sync.aligned.m8n8.x2.trans.shared.b16 {%0,%1}, [%2];"
                 : "=r"(r[0]), "=r"(r[1]) : "r"(addr));
}
static __device__ __forceinline__ void mma_f16(float* c, const uint32_t* a, uint32_t b0, uint32_t b1) {
    asm volatile("mma.sync.aligned.m16n8k16.row.col.f32.f16.f16.f32 "
                 "{%0,%1,%2,%3}, {%4,%5,%6,%7}, {%8,%9}, {%0,%1,%2,%3};"
                 : "+f"(c[0]), "+f"(c[1]), "+f"(c[2]), "+f"(c[3])
                 : "r"(a[0]), "r"(a[1]), "r"(a[2]), "r"(a[3]), "r"(b0), "r"(b1));
}
static __device__ __forceinline__ float htanh(float x) {
    float y; asm("tanh.approx.f32 %0, %1;" : "=f"(y) : "f"(x)); return y;
}

__global__ __launch_bounds__(NTHREADS, 1)
void fta_kernel(const float* __restrict__ seq,
                const float* __restrict__ dtn,
                const float* __restrict__ target,
                const int*   __restrict__ vmask,
                const float* __restrict__ fr,
                const float* __restrict__ fi,
                const float* __restrict__ Aw,
                const float* __restrict__ Ab,
                const float* __restrict__ Aout,
                float* __restrict__ out)
{
    extern __shared__ char smc[];
    const uint32_t sbase = smem_u32(smc);
    float* sTgt  = (float*)(smc + TGT_B);
    float* sAw   = (float*)(smc + AW_B);
    float* sDec  = (float*)(smc + DEC_B);
    float* sVal  = (float*)(smc + VAL_B);
    float* sAb   = (float*)(smc + AB_B);
    float* sAo   = (float*)(smc + AO_B);
    float* sFr   = (float*)(smc + FR_B);
    float* sFi   = (float*)(smc + FI_B);
    float* sPart = (float*)(smc + PART_B);

    const int b    = blockIdx.x;
    const int tid  = threadIdx.x;
    const int lane = tid & 31;
    const int warp = tid >> 5;

    // ---------------- Phase A: gmem -> smem ----------------
    {
        const float4* g4 = (const float4*)(seq + (size_t)b * TK * DD);
        for (int i = tid; i < TKP * 16; i += NTHREADS) {
            int k = i >> 4, d4 = i & 15;
            float4 v = make_float4(0.f, 0.f, 0.f, 0.f);
            if (k < TK) v = g4[k * 16 + d4];
            __half2 h01 = __floats2half2_rn(v.x, v.y);
            __half2 h23 = __floats2half2_rn(v.z, v.w);
            if (k < 208) {
                *(__half2*)(smc + SEQK_B + k * ASTRIDE + d4 * 8)     = h01;
                *(__half2*)(smc + SEQK_B + k * ASTRIDE + d4 * 8 + 4) = h23;
            }
            int d = d4 * 4;
            *(__half*)(smc + SEQT_B + (d + 0) * TSTRIDE + k * 2) = __low2half(h01);
            *(__half*)(smc + SEQT_B + (d + 1) * TSTRIDE + k * 2) = __high2half(h01);
            *(__half*)(smc + SEQT_B + (d + 2) * TSTRIDE + k * 2) = __low2half(h23);
            *(__half*)(smc + SEQT_B + (d + 3) * TSTRIDE + k * 2) = __high2half(h23);
        }
        const float* gT = target + (size_t)b * TQ * DD;
        for (int i = tid; i < TQ * DD; i += NTHREADS) {
            int t = i >> 6, d = i & 63;
            sTgt[t * 65 + d] = gT[i];
        }
        if (tid < HH * DD) sAw[tid] = Aw[tid] * 256.0f;
        if (tid < DD) { sFr[tid] = fr[tid]; sFi[tid] = fi[tid]; }
        if (tid < 16) {
            sAb[tid] = (tid < HH) ? Ab[tid]   : 0.f;
            sAo[tid] = (tid < HH) ? Aout[tid] : 0.f;
        }
    }
    __syncthreads();

    // ---------------- Phase B: Fourier decay + build ALL 10 A tiles ----------------
    if (tid < TKP) {
        float dec = 0.f, val = 0.f;
        if (tid < TK) {
            const int   m  = vmask[b * TK + tid];
            const float dt = dtn[b * TK + tid];
            const float th = (3.14159265358979323846f / 63.f) * dt;
            float acc = 0.f;
            #pragma unroll 8
            for (int j = 0; j < DD; j++) {
                float s, c;
                __sincosf(th * (float)j, &s, &c);
                acc = fmaf(c, sFr[j], acc);
                acc = fmaf(-s, sFi[j], acc);
            }
            float dcy = fminf(fmaxf(acc * (1.f / 128.f), 0.f), 1.f);
            if (m != 0) { dec = dcy; val = 1.f; }
        }
        sDec[tid] = dec;
        sVal[tid] = val;
    }
    #pragma unroll
    for (int n = 0; n < HH * 2048 / NTHREADS; n++) {       // 20 iters
        int i = tid + n * NTHREADS;
        int h = i >> 11, rem = i & 2047;
        int t = rem >> 5, dp = (rem & 31) << 1;
        float a0 = sTgt[t * 65 + dp]     * sAw[h * 64 + dp];
        float a1 = sTgt[t * 65 + dp + 1] * sAw[h * 64 + dp + 1];
        *(__half2*)(smc + ABUF_B + h * 9216 + t * ASTRIDE + dp * 2) = __floats2half2_rn(a0, a1);
    }
    __syncthreads();

    // ---------------- Phase C: score GEMM, 32 warps (4t x 8n), sync-free h-loop ----------------
    const int tg  = warp >> 3;                 // 0..3
    const int ng  = warp & 7;                  // 0..7
    const int t0  = tg * 16;
    const bool wide = (ng < 4);
    const int n0  = wide ? ng * 32 : 128 + (ng - 4) * 24;
    const int g   = lane >> 2;
    const int q2  = (lane & 3) * 2;

    float sc[16];
    {
        const uint32_t rowSel = (uint32_t)((lane & 7) + ((lane >> 3) & 1) * 8);
        const uint32_t colX4  = (uint32_t)((lane >> 4) * 8);
        const uint32_t aBase  = sbase + ABUF_B + (uint32_t)((t0 + rowSel) * ASTRIDE) + colX4 * 2;
        const uint32_t bBase  = sbase + SEQT_B + rowSel * TSTRIDE;

        #pragma unroll
        for (int i = 0; i < 16; i++) sc[i] = 0.f;

        for (int h = 0; h < HH; h++) {
            float acc[16];
            #pragma unroll
            for (int i = 0; i < 16; i++) acc[i] = 0.f;

            const uint32_t aAddr = aBase + (uint32_t)(h * 9216);
            #pragma unroll
            for (int ks = 0; ks < 4; ks++) {
                uint32_t af[4];
                ldsm_x4(af, aAddr + ks * 32);
                const uint32_t base = bBase + (uint32_t)(ks * 16) * TSTRIDE;
                uint32_t bb[8];
                ldsm_x4t(bb, base + (uint32_t)n0 * 2 + colX4 * 2);
                if (wide) ldsm_x4t(bb + 4, base + (uint32_t)(n0 + 16) * 2 + colX4 * 2);
                else      ldsm_x2t(bb + 4, base + (uint32_t)(n0 + 16) * 2);
                mma_f16(acc + 0, af, bb[0], bb[1]);
                mma_f16(acc + 4, af, bb[2], bb[3]);
                mma_f16(acc + 8, af, bb[4], bb[5]);
                if (wide) mma_f16(acc + 12, af, bb[6], bb[7]);
            }

            // sc += ao * tanh(acc/256 + ab)
            const float ao = sAo[h], abv = sAb[h];
            #pragma unroll
            for (int i = 0; i < 12; i++) {
                float x = fmaf(acc[i], 0.00390625f, abv);
                sc[i] = fmaf(ao, htanh(x), sc[i]);
            }
            if (wide) {
                #pragma unroll
                for (int i = 12; i < 16; i++) {
                    float x = fmaf(acc[i], 0.00390625f, abv);
                    sc[i] = fmaf(ao, htanh(x), sc[i]);
                }
            }
        }
    }

    // ---------------- Phase D: softmax + decay from registers -> fp16 P ----------------
    {
        float ev[16];
        float se = 0.f, so = 0.f;
        const int nOct = wide ? 4 : 3;
        #pragma unroll
        for (int o = 0; o < 4; o++) {
            if (o < nOct) {
                int c = n0 + 8 * o + q2;
                float2 v = *(float2*)&sVal[c];
                float e0 = v.x * __expf(sc[4 * o + 0]);
                float e1 = v.y * __expf(sc[4 * o + 1]);
                float e2 = v.x * __expf(sc[4 * o + 2]);
                float e3 = v.y * __expf(sc[4 * o + 3]);
                ev[4 * o + 0] = e0; ev[4 * o + 1] = e1;
                ev[4 * o + 2] = e2; ev[4 * o + 3] = e3;
                se += e0 + e1;
                so += e2 + e3;
            }
        }
        se += __shfl_xor_sync(0xffffffffu, se, 1);
        se += __shfl_xor_sync(0xffffffffu, se, 2);
        so += __shfl_xor_sync(0xffffffffu, so, 1);
        so += __shfl_xor_sync(0xffffffffu, so, 2);
        if ((lane & 3) == 0) {
            sPart[(t0 + g) * 8 + ng]     = se;
            sPart[(t0 + g + 8) * 8 + ng] = so;
        }
        __syncthreads();   // phase C reads of SEQT done + partials visible

        float4 pe0 = ((float4*)&sPart[(t0 + g) * 8])[0];
        float4 pe1 = ((float4*)&sPart[(t0 + g) * 8])[1];
        float4 po0 = ((float4*)&sPart[(t0 + g + 8) * 8])[0];
        float4 po1 = ((float4*)&sPart[(t0 + g + 8) * 8])[1];
        const float invE = __fdividef(1.f, pe0.x + pe0.y + pe0.z + pe0.w + pe1.x + pe1.y + pe1.z + pe1.w);
        const float invO = __fdividef(1.f, po0.x + po0.y + po0.z + po0.w + po1.x + po1.y + po1.z + po1.w);

        char* rowE = smc + P_B + (t0 + g) * PSTRIDE;
        char* rowO = smc + P_B + (t0 + g + 8) * PSTRIDE;
        #pragma unroll
        for (int o = 0; o < 4; o++) {
            if (o < nOct) {
                int c = n0 + 8 * o + q2;
                if (c < 216) {
                    float2 d = *(float2*)&sDec[c];
                    *(__half2*)(rowE + c * 2) =
                        __floats2half2_rn(ev[4 * o + 0] * invE * d.x, ev[4 * o + 1] * invE * d.y);
                    *(__half2*)(rowO + c * 2) =
                        __floats2half2_rn(ev[4 * o + 2] * invO * d.x, ev[4 * o + 3] * invO * d.y);
                }
            }
        }
    }
    __syncthreads();

    // ---------------- Phase E: context = P @ seq via MMA (32 warps: 16t x 8d) ----------------
    {
        const int t0e = (warp >> 3) * 16;
        const int d0  = (warp & 7) * 8;
        const uint32_t rowSel = (uint32_t)((lane & 7) + ((lane >> 3) & 1) * 8);
        const uint32_t pBase = sbase + P_B + (uint32_t)((t0e + rowSel) * PSTRIDE) + (uint32_t)((lane >> 4) * 16);
        const uint32_t kBase = sbase + SEQK_B + rowSel * ASTRIDE + (uint32_t)(d0 * 2);

        float accA[4] = {0.f, 0.f, 0.f, 0.f};
        #pragma unroll
        for (int kc = 0; kc < 13; kc++) {
            uint32_t a[4], bb[2];
            ldsm_x4(a, pBase + (uint32_t)(kc * 32));
            ldsm_x2t(bb, kBase + (uint32_t)(kc * 16) * ASTRIDE);
            mma_f16(accA, a, bb[0], bb[1]);
        }
        float* gout = out + (size_t)b * TQ * DD;
        const int rr = lane >> 2, cc = (lane & 3) * 2;
        *(float2*)(gout + (t0e + rr) * 64 + d0 + cc)     = make_float2(accA[0], accA[1]);
        *(float2*)(gout + (t0e + rr + 8) * 64 + d0 + cc) = make_float2(accA[2], accA[3]);
    }
}

extern "C" void kernel_launch(void* const* d_in, const int* in_sizes, int n_in,
                              void* d_out, int out_size)
{
    const float* seq    = (const float*)d_in[0];
    const float* dtn    = (const float*)d_in[1];
    const float* target = (const float*)d_in[2];
    const int*   vmask  = (const int*)  d_in[3];
    const float* fr     = (const float*)d_in[4];
    const float* fi     = (const float*)d_in[5];
    const float* Aw     = (const float*)d_in[6];
    const float* Ab     = (const float*)d_in[7];
    const float* Aout   = (const float*)d_in[8];
    float* out = (float*)d_out;

    cudaFuncSetAttribute(fta_kernel, cudaFuncAttributeMaxDynamicSharedMemorySize, SMEM_TOTAL_B);
    fta_kernel<<<BB, NTHREADS, SMEM_TOTAL_B>>>(seq, dtn, target, vmask, fr, fi, Aw, Ab, Aout, out);
}

// round 8
// speedup vs baseline: 1.0448x; 1.0448x over previous
#include <cuda_runtime.h>
#include <cuda_fp16.h>
#include <cstdint>

#define BB 128
#define TQ 64
#define TK 200
#define TKP 224
#define DD 64
#define HH 10
#define NTHREADS 896

#define TSTRIDE 464            // seqT row stride bytes (fp16, 224 cols + pad)
#define ASTRIDE 144            // A / SEQK row stride bytes (72 fp16)
#define PSTRIDE 432            // P row stride bytes (216 fp16)

// ---- smem byte offsets ----
#define SEQT_B   0             // fp16 seq transposed [64d][464B]      29,696
#define P_B      0             // alias: fp16 P [64t][432B] (phase D/E)
#define SEQK_B   29696         // fp16 seq k-major [208][144B]         29,952
#define ABUF_B   59648         // fp16 A[10][64t][144B]                92,160
#define TGT_B    151808        // float [64][65]                       16,640
#define AW_B     168448        // float [10][64] (x256)                 2,560
#define DEC_B    171008        // float [224]                             896
#define VAL_B    171904        // float [224]                             896
#define AB_B     172800        // float [16]
#define AO_B     172864        // float [16]
#define FR_B     172928        // float [64]
#define FI_B     173184        // float [64]
#define PART_B   173440        // float [64][8] row partial sums        2,048
#define SMEM_TOTAL_B 175488

static __device__ __forceinline__ uint32_t smem_u32(const void* p) {
    uint32_t a;
    asm("{ .reg .u64 t; cvta.to.shared.u64 t, %1; cvt.u32.u64 %0, t; }" : "=r"(a) : "l"(p));
    return a;
}
static __device__ __forceinline__ void ldsm_x4(uint32_t* r, uint32_t addr) {
    asm volatile("ldmatrix.sync.aligned.m8n8.x4.shared.b16 {%0,%1,%2,%3}, [%4];"
                 : "=r"(r[0]), "=r"(r[1]), "=r"(r[2]), "=r"(r[3]) : "r"(addr));
}
static __device__ __forceinline__ void ldsm_x4t(uint32_t* r, uint32_t addr) {
    asm volatile("ldmatrix.sync.aligned.m8n8.x4.trans.shared.b16 {%0,%1,%2,%3}, [%4];"
                 : "=r"(r[0]), "=r"(r[1]), "=r"(r[2]), "=r"(r[3]) : "r"(addr));
}
static __device__ __forceinline__ void ldsm_x2t(uint32_t* r, uint32_t addr) {
    asm volatile("ldmatrix.sync.aligned.m8n8.x2.trans.shared.b16 {%0,%1}, [%2];"
                 : "=r"(r[0]), "=r"(r[1]) : "r"(addr));
}
static __device__ __forceinline__ void mma_f16(float* c, const uint32_t* a, uint32_t b0, uint32_t b1) {
    asm volatile("mma.sync.aligned.m16n8k16.row.col.f32.f16.f16.f32 "
                 "{%0,%1,%2,%3}, {%4,%5,%6,%7}, {%8,%9}, {%0,%1,%2,%3};"
                 : "+f"(c[0]), "+f"(c[1]), "+f"(c[2]), "+f"(c[3])
                 : "r"(a[0]), "r"(a[1]), "r"(a[2]), "r"(a[3]), "r"(b0), "r"(b1));
}
static __device__ __forceinline__ float htanh(float x) {
    float y; asm("tanh.approx.f32 %0, %1;" : "=f"(y) : "f"(x)); return y;
}

__global__ __launch_bounds__(NTHREADS, 1)
void fta_kernel(const float* __restrict__ seq,
                const float* __restrict__ dtn,
                const float* __restrict__ target,
                const int*   __restrict__ vmask,
                const float* __restrict__ fr,
                const float* __restrict__ fi,
                const float* __restrict__ Aw,
                const float* __restrict__ Ab,
                const float* __restrict__ Aout,
                float* __restrict__ out)
{
    extern __shared__ char smc[];
    const uint32_t sbase = smem_u32(smc);
    float* sTgt  = (float*)(smc + TGT_B);
    float* sAw   = (float*)(smc + AW_B);
    float* sDec  = (float*)(smc + DEC_B);
    float* sVal  = (float*)(smc + VAL_B);
    float* sAb   = (float*)(smc + AB_B);
    float* sAo   = (float*)(smc + AO_B);
    float* sFr   = (float*)(smc + FR_B);
    float* sFi   = (float*)(smc + FI_B);
    float* sPart = (float*)(smc + PART_B);

    const int b    = blockIdx.x;
    const int tid  = threadIdx.x;
    const int lane = tid & 31;
    const int warp = tid >> 5;

    // ---------------- Phase A: gmem -> smem ----------------
    {
        const float4* g4 = (const float4*)(seq + (size_t)b * TK * DD);
        #pragma unroll
        for (int n = 0; n < TKP * 16 / NTHREADS; n++) {    // 4 iters
            int i = tid + n * NTHREADS;
            int k = i >> 4, d4 = i & 15;
            float4 v = make_float4(0.f, 0.f, 0.f, 0.f);
            if (k < TK) v = g4[k * 16 + d4];
            __half2 h01 = __floats2half2_rn(v.x, v.y);
            __half2 h23 = __floats2half2_rn(v.z, v.w);
            if (k < 208) {
                *(__half2*)(smc + SEQK_B + k * ASTRIDE + d4 * 8)     = h01;
                *(__half2*)(smc + SEQK_B + k * ASTRIDE + d4 * 8 + 4) = h23;
            }
            int d = d4 * 4;
            *(__half*)(smc + SEQT_B + (d + 0) * TSTRIDE + k * 2) = __low2half(h01);
            *(__half*)(smc + SEQT_B + (d + 1) * TSTRIDE + k * 2) = __high2half(h01);
            *(__half*)(smc + SEQT_B + (d + 2) * TSTRIDE + k * 2) = __low2half(h23);
            *(__half*)(smc + SEQT_B + (d + 3) * TSTRIDE + k * 2) = __high2half(h23);
        }
        const float* gT = target + (size_t)b * TQ * DD;
        for (int i = tid; i < TQ * DD; i += NTHREADS) {
            int t = i >> 6, d = i & 63;
            sTgt[t * 65 + d] = gT[i];
        }
        if (tid < HH * DD) sAw[tid] = Aw[tid] * 256.0f;
        if (tid < DD) { sFr[tid] = fr[tid]; sFi[tid] = fi[tid]; }
        if (tid < 16) {
            sAb[tid] = (tid < HH) ? Ab[tid]   : 0.f;
            sAo[tid] = (tid < HH) ? Aout[tid] : 0.f;
        }
        if (tid < 512) sPart[tid] = 0.f;                   // zero (incl. pad col 7)
    }
    __syncthreads();

    // ---------------- Phase B: Fourier decay + build ALL 10 A tiles ----------------
    if (tid < TKP) {
        float dec = 0.f, val = 0.f;
        if (tid < TK) {
            const int   m  = vmask[b * TK + tid];
            const float dt = dtn[b * TK + tid];
            const float th = (3.14159265358979323846f / 63.f) * dt;
            float acc = 0.f;
            #pragma unroll 8
            for (int j = 0; j < DD; j++) {
                float s, c;
                __sincosf(th * (float)j, &s, &c);
                acc = fmaf(c, sFr[j], acc);
                acc = fmaf(-s, sFi[j], acc);
            }
            float dcy = fminf(fmaxf(acc * (1.f / 128.f), 0.f), 1.f);
            if (m != 0) { dec = dcy; val = 1.f; }
        }
        sDec[tid] = dec;
        sVal[tid] = val;
    }
    for (int i = tid; i < HH * 2048; i += NTHREADS) {
        int h = i >> 11, rem = i & 2047;
        int t = rem >> 5, dp = (rem & 31) << 1;
        float a0 = sTgt[t * 65 + dp]     * sAw[h * 64 + dp];
        float a1 = sTgt[t * 65 + dp + 1] * sAw[h * 64 + dp + 1];
        *(__half2*)(smc + ABUF_B + h * 9216 + t * ASTRIDE + dp * 2) = __floats2half2_rn(a0, a1);
    }
    __syncthreads();

    // ---------------- Phase C: score GEMM, 28 warps (4t x 7n, n=32), h-pairs share B ----------------
    const int tg  = warp / 7;                  // 0..3
    const int ng  = warp % 7;                  // 0..6
    const int t0  = tg * 16;
    const int n0  = ng * 32;
    const int g   = lane >> 2;
    const int q2  = (lane & 3) * 2;

    float sc[16];
    {
        const uint32_t rowSel = (uint32_t)((lane & 7) + ((lane >> 3) & 1) * 8);
        const uint32_t colX4  = (uint32_t)((lane >> 4) * 8);
        const uint32_t aBase  = sbase + ABUF_B + (uint32_t)((t0 + rowSel) * ASTRIDE) + colX4 * 2;
        const uint32_t bBase  = sbase + SEQT_B + rowSel * TSTRIDE + (uint32_t)n0 * 2 + colX4 * 2;

        #pragma unroll
        for (int i = 0; i < 16; i++) sc[i] = 0.f;

        for (int h = 0; h < HH; h += 2) {
            float acc0[16], acc1[16];
            #pragma unroll
            for (int i = 0; i < 16; i++) { acc0[i] = 0.f; acc1[i] = 0.f; }

            const uint32_t aA0 = aBase + (uint32_t)(h * 9216);
            const uint32_t aA1 = aA0 + 9216;
            #pragma unroll
            for (int ks = 0; ks < 4; ks++) {
                uint32_t bb[8];
                const uint32_t base = bBase + (uint32_t)(ks * 16) * TSTRIDE;
                ldsm_x4t(bb,     base);
                ldsm_x4t(bb + 4, base + 32);               // +16 cols
                uint32_t af0[4], af1[4];
                ldsm_x4(af0, aA0 + ks * 32);
                ldsm_x4(af1, aA1 + ks * 32);
                #pragma unroll
                for (int j = 0; j < 4; j++) mma_f16(acc0 + 4 * j, af0, bb[2 * j], bb[2 * j + 1]);
                #pragma unroll
                for (int j = 0; j < 4; j++) mma_f16(acc1 + 4 * j, af1, bb[2 * j], bb[2 * j + 1]);
            }

            const float ao0 = sAo[h],     ab0 = sAb[h];
            const float ao1 = sAo[h + 1], ab1 = sAb[h + 1];
            #pragma unroll
            for (int i = 0; i < 16; i++) {
                float x0 = fmaf(acc0[i], 0.00390625f, ab0);
                float x1 = fmaf(acc1[i], 0.00390625f, ab1);
                sc[i] = fmaf(ao0, htanh(x0), sc[i]);
                sc[i] = fmaf(ao1, htanh(x1), sc[i]);
            }
        }
    }

    // ---------------- Phase D: softmax + decay from registers -> fp16 P ----------------
    {
        float ev[16];
        float se = 0.f, so = 0.f;
        #pragma unroll
        for (int o = 0; o < 4; o++) {
            int c = n0 + 8 * o + q2;
            float2 v = *(float2*)&sVal[c];
            float e0 = v.x * __expf(sc[4 * o + 0]);
            float e1 = v.y * __expf(sc[4 * o + 1]);
            float e2 = v.x * __expf(sc[4 * o + 2]);
            float e3 = v.y * __expf(sc[4 * o + 3]);
            ev[4 * o + 0] = e0; ev[4 * o + 1] = e1;
            ev[4 * o + 2] = e2; ev[4 * o + 3] = e3;
            se += e0 + e1;
            so += e2 + e3;
        }
        se += __shfl_xor_sync(0xffffffffu, se, 1);
        se += __shfl_xor_sync(0xffffffffu, se, 2);
        so += __shfl_xor_sync(0xffffffffu, so, 1);
        so += __shfl_xor_sync(0xffffffffu, so, 2);
        if ((lane & 3) == 0) {
            sPart[(t0 + g) * 8 + ng]     = se;
            sPart[(t0 + g + 8) * 8 + ng] = so;
        }
        __syncthreads();   // phase C reads of SEQT done + partials visible

        float4 pe0 = ((float4*)&sPart[(t0 + g) * 8])[0];
        float4 pe1 = ((float4*)&sPart[(t0 + g) * 8])[1];
        float4 po0 = ((float4*)&sPart[(t0 + g + 8) * 8])[0];
        float4 po1 = ((float4*)&sPart[(t0 + g + 8) * 8])[1];
        const float invE = __fdividef(1.f, pe0.x + pe0.y + pe0.z + pe0.w + pe1.x + pe1.y + pe1.z + pe1.w);
        const float invO = __fdividef(1.f, po0.x + po0.y + po0.z + po0.w + po1.x + po1.y + po1.z + po1.w);

        char* rowE = smc + P_B + (t0 + g) * PSTRIDE;
        char* rowO = smc + P_B + (t0 + g + 8) * PSTRIDE;
        #pragma unroll
        for (int o = 0; o < 4; o++) {
            int c = n0 + 8 * o + q2;
            if (c < 216) {
                float2 d = *(float2*)&sDec[c];
                *(__half2*)(rowE + c * 2) =
                    __floats2half2_rn(ev[4 * o + 0] * invE * d.x, ev[4 * o + 1] * invE * d.y);
                *(__half2*)(rowO + c * 2) =
                    __floats2half2_rn(ev[4 * o + 2] * invO * d.x, ev[4 * o + 3] * invO * d.y);
            }
        }
    }
    __syncthreads();

    // ---------------- Phase E: context = P @ seq via MMA (32 tiles over 28 warps) ----------------
    {
        const uint32_t rowSel = (uint32_t)((lane & 7) + ((lane >> 3) & 1) * 8);
        const int rr = lane >> 2, cc = (lane & 3) * 2;
        float* gout = out + (size_t)b * TQ * DD;

        for (int tile = warp; tile < 32; tile += 28) {
            const int t0e = (tile >> 3) * 16;
            const int d0  = (tile & 7) * 8;
            const uint32_t pBase = sbase + P_B + (uint32_t)((t0e + rowSel) * PSTRIDE) + (uint32_t)((lane >> 4) * 16);
            const uint32_t kBase = sbase + SEQK_B + rowSel * ASTRIDE + (uint32_t)(d0 * 2);

            float accA[4] = {0.f, 0.f, 0.f, 0.f};
            #pragma unroll
            for (int kc = 0; kc < 13; kc++) {
                uint32_t a[4], bb2[2];
                ldsm_x4(a, pBase + (uint32_t)(kc * 32));
                ldsm_x2t(bb2, kBase + (uint32_t)(kc * 16) * ASTRIDE);
                mma_f16(accA, a, bb2[0], bb2[1]);
            }
            *(float2*)(gout + (t0e + rr) * 64 + d0 + cc)     = make_float2(accA[0], accA[1]);
            *(float2*)(gout + (t0e + rr + 8) * 64 + d0 + cc) = make_float2(accA[2], accA[3]);
        }
    }
}

extern "C" void kernel_launch(void* const* d_in, const int* in_sizes, int n_in,
                              void* d_out, int out_size)
{
    const float* seq    = (const float*)d_in[0];
    const float* dtn    = (const float*)d_in[1];
    const float* target = (const float*)d_in[2];
    const int*   vmask  = (const int*)  d_in[3];
    const float* fr     = (const float*)d_in[4];
    const float* fi     = (const float*)d_in[5];
    const float* Aw     = (const float*)d_in[6];
    const float* Ab     = (const float*)d_in[7];
    const float* Aout   = (const float*)d_in[8];
    float* out = (float*)d_out;

    cudaFuncSetAttribute(fta_kernel, cudaFuncAttributeMaxDynamicSharedMemorySize, SMEM_TOTAL_B);
    fta_kernel<<<BB, NTHREADS, SMEM_TOTAL_B>>>(seq, dtn, target, vmask, fr, fi, Aw, Ab, Aout, out);
}

// round 9
// speedup vs baseline: 1.1325x; 1.0839x over previous
#include <cuda_runtime.h>
#include <cuda_fp16.h>
#include <cstdint>

#define BB 128
#define TQ 64
#define TK 200
#define TKP 224
#define DD 64
#define HH 10
#define NTHREADS 896

#define ASTRIDE 144            // A / SEQK row stride bytes (72 fp16)
#define PSTRIDE 432            // P row stride bytes (216 fp16)

// ---- smem byte offsets ----
#define SEQK_B   0             // fp16 seq k-major [224][144B]         32,256
#define ABUF_B   32256         // fp16 A[10][64t][144B]                92,160
#define P_B      124416        // fp16 P [64t][432B]                   27,648
#define TGT_B    152064        // float [64][65]                       16,640
#define AW_B     168704        // float [10][64] (x256)                 2,560
#define DEC_B    171264        // float [224]                             896
#define VAL_B    172160        // float [224]                             896
#define AB_B     173056        // float [16]
#define AO_B     173120        // float [16]
#define FR_B     173184        // float [64]
#define FI_B     173440        // float [64]
#define PART_B   173696        // float [64][8] row partial sums        2,048
#define SMEM_TOTAL_B 175744

static __device__ __forceinline__ uint32_t smem_u32(const void* p) {
    uint32_t a;
    asm("{ .reg .u64 t; cvta.to.shared.u64 t, %1; cvt.u32.u64 %0, t; }" : "=r"(a) : "l"(p));
    return a;
}
static __device__ __forceinline__ void ldsm_x4(uint32_t* r, uint32_t addr) {
    asm volatile("ldmatrix.sync.aligned.m8n8.x4.shared.b16 {%0,%1,%2,%3}, [%4];"
                 : "=r"(r[0]), "=r"(r[1]), "=r"(r[2]), "=r"(r[3]) : "r"(addr));
}
static __device__ __forceinline__ void ldsm_x2(uint32_t* r, uint32_t addr) {
    asm volatile("ldmatrix.sync.aligned.m8n8.x2.shared.b16 {%0,%1}, [%2];"
                 : "=r"(r[0]), "=r"(r[1]) : "r"(addr));
}
static __device__ __forceinline__ void ldsm_x2t(uint32_t* r, uint32_t addr) {
    asm volatile("ldmatrix.sync.aligned.m8n8.x2.trans.shared.b16 {%0,%1}, [%2];"
                 : "=r"(r[0]), "=r"(r[1]) : "r"(addr));
}
static __device__ __forceinline__ void mma_f16(float* c, const uint32_t* a, uint32_t b0, uint32_t b1) {
    asm volatile("mma.sync.aligned.m16n8k16.row.col.f32.f16.f16.f32 "
                 "{%0,%1,%2,%3}, {%4,%5,%6,%7}, {%8,%9}, {%0,%1,%2,%3};"
                 : "+f"(c[0]), "+f"(c[1]), "+f"(c[2]), "+f"(c[3])
                 : "r"(a[0]), "r"(a[1]), "r"(a[2]), "r"(a[3]), "r"(b0), "r"(b1));
}
static __device__ __forceinline__ float htanh(float x) {
    float y; asm("tanh.approx.f32 %0, %1;" : "=f"(y) : "f"(x)); return y;
}

__global__ __launch_bounds__(NTHREADS, 1)
void fta_kernel(const float* __restrict__ seq,
                const float* __restrict__ dtn,
                const float* __restrict__ target,
                const int*   __restrict__ vmask,
                const float* __restrict__ fr,
                const float* __restrict__ fi,
                const float* __restrict__ Aw,
                const float* __restrict__ Ab,
                const float* __restrict__ Aout,
                float* __restrict__ out)
{
    extern __shared__ char smc[];
    const uint32_t sbase = smem_u32(smc);
    float* sTgt  = (float*)(smc + TGT_B);
    float* sAw   = (float*)(smc + AW_B);
    float* sDec  = (float*)(smc + DEC_B);
    float* sVal  = (float*)(smc + VAL_B);
    float* sAb   = (float*)(smc + AB_B);
    float* sAo   = (float*)(smc + AO_B);
    float* sFr   = (float*)(smc + FR_B);
    float* sFi   = (float*)(smc + FI_B);
    float* sPart = (float*)(smc + PART_B);

    const int b    = blockIdx.x;
    const int tid  = threadIdx.x;
    const int lane = tid & 31;
    const int warp = tid >> 5;

    // ---------------- Phase A: gmem -> smem (SEQK only; no transpose!) ----------------
    {
        const float4* g4 = (const float4*)(seq + (size_t)b * TK * DD);
        #pragma unroll
        for (int n = 0; n < TKP * 16 / NTHREADS; n++) {    // 4 iters
            int i = tid + n * NTHREADS;
            int k = i >> 4, d4 = i & 15;
            float4 v = make_float4(0.f, 0.f, 0.f, 0.f);
            if (k < TK) v = g4[k * 16 + d4];
            *(__half2*)(smc + SEQK_B + k * ASTRIDE + d4 * 8)     = __floats2half2_rn(v.x, v.y);
            *(__half2*)(smc + SEQK_B + k * ASTRIDE + d4 * 8 + 4) = __floats2half2_rn(v.z, v.w);
        }
        const float* gT = target + (size_t)b * TQ * DD;
        for (int i = tid; i < TQ * DD; i += NTHREADS) {
            int t = i >> 6, d = i & 63;
            sTgt[t * 65 + d] = gT[i];
        }
        if (tid < HH * DD) sAw[tid] = Aw[tid] * 256.0f;
        if (tid < DD) { sFr[tid] = fr[tid]; sFi[tid] = fi[tid]; }
        if (tid < 16) {
            sAb[tid] = (tid < HH) ? Ab[tid]   : 0.f;
            sAo[tid] = (tid < HH) ? Aout[tid] : 0.f;
        }
        if (tid < 512) {
            sPart[tid] = 0.f;                              // zero partials (incl. pad col 7)
            // zero P columns 200-215 (bytes 400..431) for phase E's 13th k-chunk
            int row = tid >> 3, off = 400 + (tid & 7) * 4;
            *(uint32_t*)(smc + P_B + row * PSTRIDE + off) = 0u;
        }
    }
    __syncthreads();

    // ---------------- Phase B: Fourier decay + build ALL 10 A tiles ----------------
    if (tid < TKP) {
        float dec = 0.f, val = 0.f;
        if (tid < TK) {
            const int   m  = vmask[b * TK + tid];
            const float dt = dtn[b * TK + tid];
            const float th = (3.14159265358979323846f / 63.f) * dt;
            float acc = 0.f;
            #pragma unroll 8
            for (int j = 0; j < DD; j++) {
                float s, c;
                __sincosf(th * (float)j, &s, &c);
                acc = fmaf(c, sFr[j], acc);
                acc = fmaf(-s, sFi[j], acc);
            }
            float dcy = fminf(fmaxf(acc * (1.f / 128.f), 0.f), 1.f);
            if (m != 0) { dec = dcy; val = 1.f; }
        }
        sDec[tid] = dec;
        sVal[tid] = val;
    }
    for (int i = tid; i < HH * 2048; i += NTHREADS) {
        int h = i >> 11, rem = i & 2047;
        int t = rem >> 5, dp = (rem & 31) << 1;
        float a0 = sTgt[t * 65 + dp]     * sAw[h * 64 + dp];
        float a1 = sTgt[t * 65 + dp + 1] * sAw[h * 64 + dp + 1];
        *(__half2*)(smc + ABUF_B + h * 9216 + t * ASTRIDE + dp * 2) = __floats2half2_rn(a0, a1);
    }
    __syncthreads();

    // ---------------- Phase C: TN score GEMM (non-trans B!), 28 warps, h-pairs share B ----------------
    const int tg  = warp / 7;                  // 0..3
    const int ng  = warp % 7;                  // 0..6
    const int t0  = tg * 16;
    const bool wide = (ng < 4);
    const int n0  = wide ? ng * 32 : 128 + (ng - 4) * 24;  // 4x32 + 3x24 = 200 cols exactly
    const int g   = lane >> 2;
    const int q2  = (lane & 3) * 2;

    float sc[16];
    {
        // A fragment address (row-major A tile, k=d contiguous)
        const uint32_t rowSel = (uint32_t)((lane & 7) + ((lane >> 3) & 1) * 8);
        const uint32_t aBase  = sbase + ABUF_B + (uint32_t)((t0 + rowSel) * ASTRIDE)
                              + (uint32_t)((lane >> 4) * 16);
        // B fragment address (col-major B = seq[k_token][d], d contiguous) — non-trans ldsm
        const uint32_t bRow   = (uint32_t)(n0 + (lane & 7) + ((lane >> 4) << 3));
        const uint32_t bBase  = sbase + SEQK_B + bRow * ASTRIDE + (uint32_t)(((lane >> 3) & 1) * 16);
        // narrow-warp third octet (x2: lanes 0-15 supply addresses)
        const uint32_t b2Base = sbase + SEQK_B + (uint32_t)((n0 + 16 + (lane & 7)) * ASTRIDE)
                              + (uint32_t)(((lane >> 3) & 1) * 16);

        #pragma unroll
        for (int i = 0; i < 16; i++) sc[i] = 0.f;

        for (int h = 0; h < HH; h += 2) {
            float acc0[16], acc1[16];
            #pragma unroll
            for (int i = 0; i < 16; i++) { acc0[i] = 0.f; acc1[i] = 0.f; }

            const uint32_t aA0 = aBase + (uint32_t)(h * 9216);
            const uint32_t aA1 = aA0 + 9216;
            #pragma unroll
            for (int ks = 0; ks < 4; ks++) {
                const uint32_t d0b = (uint32_t)(ks * 32);
                uint32_t bb[8];
                ldsm_x4(bb, bBase + d0b);                       // tokens n0..n0+15
                if (wide) ldsm_x4(bb + 4, bBase + 2304 + d0b);  // tokens n0+16..n0+31
                else      ldsm_x2(bb + 4, b2Base + d0b);        // tokens n0+16..n0+23
                uint32_t af0[4], af1[4];
                ldsm_x4(af0, aA0 + d0b);
                ldsm_x4(af1, aA1 + d0b);
                mma_f16(acc0 + 0, af0, bb[0], bb[1]);
                mma_f16(acc0 + 4, af0, bb[2], bb[3]);
                mma_f16(acc0 + 8, af0, bb[4], bb[5]);
                mma_f16(acc1 + 0, af1, bb[0], bb[1]);
                mma_f16(acc1 + 4, af1, bb[2], bb[3]);
                mma_f16(acc1 + 8, af1, bb[4], bb[5]);
                if (wide) {
                    mma_f16(acc0 + 12, af0, bb[6], bb[7]);
                    mma_f16(acc1 + 12, af1, bb[6], bb[7]);
                }
            }

            const float ao0 = sAo[h],     ab0 = sAb[h];
            const float ao1 = sAo[h + 1], ab1 = sAb[h + 1];
            const int nel = wide ? 16 : 12;
            #pragma unroll
            for (int i = 0; i < 16; i++) {
                if (i < nel) {
                    float x0 = fmaf(acc0[i], 0.00390625f, ab0);
                    float x1 = fmaf(acc1[i], 0.00390625f, ab1);
                    sc[i] = fmaf(ao0, htanh(x0), sc[i]);
                    sc[i] = fmaf(ao1, htanh(x1), sc[i]);
                }
            }
        }
    }

    // ---------------- Phase D: softmax + decay from registers -> fp16 P ----------------
    {
        const int nOct = wide ? 4 : 3;
        float ev[16];
        float se = 0.f, so = 0.f;
        #pragma unroll
        for (int o = 0; o < 4; o++) {
            if (o < nOct) {
                int c = n0 + 8 * o + q2;
                float2 v = *(float2*)&sVal[c];
                float e0 = v.x * __expf(sc[4 * o + 0]);
                float e1 = v.y * __expf(sc[4 * o + 1]);
                float e2 = v.x * __expf(sc[4 * o + 2]);
                float e3 = v.y * __expf(sc[4 * o + 3]);
                ev[4 * o + 0] = e0; ev[4 * o + 1] = e1;
                ev[4 * o + 2] = e2; ev[4 * o + 3] = e3;
                se += e0 + e1;
                so += e2 + e3;
            }
        }
        se += __shfl_xor_sync(0xffffffffu, se, 1);
        se += __shfl_xor_sync(0xffffffffu, se, 2);
        so += __shfl_xor_sync(0xffffffffu, so, 1);
        so += __shfl_xor_sync(0xffffffffu, so, 2);
        if ((lane & 3) == 0) {
            sPart[(t0 + g) * 8 + ng]     = se;
            sPart[(t0 + g + 8) * 8 + ng] = so;
        }
        __syncthreads();   // phase C smem reads done + partials visible

        float4 pe0 = ((float4*)&sPart[(t0 + g) * 8])[0];
        float4 pe1 = ((float4*)&sPart[(t0 + g) * 8])[1];
        float4 po0 = ((float4*)&sPart[(t0 + g + 8) * 8])[0];
        float4 po1 = ((float4*)&sPart[(t0 + g + 8) * 8])[1];
        const float invE = __fdividef(1.f, pe0.x + pe0.y + pe0.z + pe0.w + pe1.x + pe1.y + pe1.z + pe1.w);
        const float invO = __fdividef(1.f, po0.x + po0.y + po0.z + po0.w + po1.x + po1.y + po1.z + po1.w);

        char* rowE = smc + P_B + (t0 + g) * PSTRIDE;
        char* rowO = smc + P_B + (t0 + g + 8) * PSTRIDE;
        #pragma unroll
        for (int o = 0; o < 4; o++) {
            if (o < nOct) {
                int c = n0 + 8 * o + q2;
                float2 d = *(float2*)&sDec[c];
                *(__half2*)(rowE + c * 2) =
                    __floats2half2_rn(ev[4 * o + 0] * invE * d.x, ev[4 * o + 1] * invE * d.y);
                *(__half2*)(rowO + c * 2) =
                    __floats2half2_rn(ev[4 * o + 2] * invO * d.x, ev[4 * o + 3] * invO * d.y);
            }
        }
    }
    __syncthreads();

    // ---------------- Phase E: context = P @ seq via MMA (32 tiles over 28 warps) ----------------
    {
        const uint32_t rowSel = (uint32_t)((lane & 7) + ((lane >> 3) & 1) * 8);
        const int rr = lane >> 2, cc = (lane & 3) * 2;
        float* gout = out + (size_t)b * TQ * DD;

        for (int tile = warp; tile < 32; tile += 28) {
            const int t0e = (tile >> 3) * 16;
            const int d0  = (tile & 7) * 8;
            const uint32_t pBase = sbase + P_B + (uint32_t)((t0e + rowSel) * PSTRIDE) + (uint32_t)((lane >> 4) * 16);
            const uint32_t kBase = sbase + SEQK_B + rowSel * ASTRIDE + (uint32_t)(d0 * 2);

            float accA[4] = {0.f, 0.f, 0.f, 0.f};
            #pragma unroll
            for (int kc = 0; kc < 13; kc++) {
                uint32_t a[4], bb2[2];
                ldsm_x4(a, pBase + (uint32_t)(kc * 32));
                ldsm_x2t(bb2, kBase + (uint32_t)(kc * 16) * ASTRIDE);
                mma_f16(accA, a, bb2[0], bb2[1]);
            }
            *(float2*)(gout + (t0e + rr) * 64 + d0 + cc)     = make_float2(accA[0], accA[1]);
            *(float2*)(gout + (t0e + rr + 8) * 64 + d0 + cc) = make_float2(accA[2], accA[3]);
        }
    }
}

extern "C" void kernel_launch(void* const* d_in, const int* in_sizes, int n_in,
                              void* d_out, int out_size)
{
    const float* seq    = (const float*)d_in[0];
    const float* dtn    = (const float*)d_in[1];
    const float* target = (const float*)d_in[2];
    const int*   vmask  = (const int*)  d_in[3];
    const float* fr     = (const float*)d_in[4];
    const float* fi     = (const float*)d_in[5];
    const float* Aw     = (const float*)d_in[6];
    const float* Ab     = (const float*)d_in[7];
    const float* Aout   = (const float*)d_in[8];
    float* out = (float*)d_out;

    cudaFuncSetAttribute(fta_kernel, cudaFuncAttributeMaxDynamicSharedMemorySize, SMEM_TOTAL_B);
    fta_kernel<<<BB, NTHREADS, SMEM_TOTAL_B>>>(seq, dtn, target, vmask, fr, fi, Aw, Ab, Aout, out);
}